// round 1
// baseline (speedup 1.0000x reference)
#include <cuda_runtime.h>
#include <cuda_bf16.h>

#define BSZ 2
#define LSEQ 1024
#define DM 768
#define DI 1536
#define DS 16
#define DC 4
#define DTR 48
#define NL 24
#define RWS (BSZ*LSEQ)          /* 2048 token rows per direction */
#define DBLW (DTR + 2*DS)       /* 80 */
#define EPSF 1e-5f

// ---------------------------------------------------------------------------
// Scratch (device globals; allocation-free per harness rules)
// ---------------------------------------------------------------------------
__device__ float g_x[2][RWS*DM];        // layer input (per dir)
__device__ float g_h[2][RWS*DM];        // rmsnorm output
__device__ float g_xz[2][RWS*2*DI];     // in_proj output (xs | z)
__device__ float g_xc[2][RWS*DI];       // conv+silu output
__device__ float g_dbl[2][RWS*DBLW];    // x_proj output (dt | B | C)
__device__ float g_delta[2][RWS*DI];    // softplus(dt@dt_w + dt_b)
__device__ float g_y[2][RWS*DI];        // scan output (gated)

__device__ __forceinline__ float* getbuf(int w, int dir) {
    switch (w) {
        case 0: return g_h[dir];
        case 1: return g_xz[dir];
        case 2: return g_xc[dir];
        case 3: return g_dbl[dir];
        case 4: return g_delta[dir];
        case 5: return g_y[dir];
        default: return g_x[dir];
    }
}

// ---------------------------------------------------------------------------
// Embedding (+ sequence flip for the backward stack)
// ---------------------------------------------------------------------------
__global__ void k_embed(const int* __restrict__ ids,
                        const float* __restrict__ embF,
                        const float* __restrict__ embB) {
    int row = blockIdx.x;            // b*LSEQ + l
    int dir = blockIdx.y;
    int b = row / LSEQ, l = row % LSEQ;
    int tok = (dir == 0) ? ids[b*LSEQ + l] : ids[b*LSEQ + (LSEQ-1-l)];
    const float* emb = (dir == 0) ? embF : embB;
    const float4* src = (const float4*)(emb + (size_t)tok * DM);
    float4* dst = (float4*)(g_x[dir] + (size_t)row * DM);
    for (int i = threadIdx.x; i < DM/4; i += blockDim.x) dst[i] = src[i];
}

// ---------------------------------------------------------------------------
// RMSNorm
// ---------------------------------------------------------------------------
__global__ void k_rmsnorm(const float* __restrict__ wF,
                          const float* __restrict__ wB) {
    int row = blockIdx.x, dir = blockIdx.y;
    const float* x = g_x[dir] + (size_t)row * DM;
    float* h = g_h[dir] + (size_t)row * DM;
    const float* w = dir ? wB : wF;
    float s = 0.f;
    for (int i = threadIdx.x; i < DM; i += 256) { float v = x[i]; s += v*v; }
    #pragma unroll
    for (int o = 16; o; o >>= 1) s += __shfl_down_sync(0xffffffffu, s, o);
    __shared__ float red[8];
    if ((threadIdx.x & 31) == 0) red[threadIdx.x >> 5] = s;
    __syncthreads();
    if (threadIdx.x < 8) {
        float t = red[threadIdx.x];
        #pragma unroll
        for (int o = 4; o; o >>= 1) t += __shfl_down_sync(0xffu, t, o);
        if (threadIdx.x == 0) red[0] = t;
    }
    __syncthreads();
    float inv = rsqrtf(red[0] / (float)DM + EPSF);
    for (int i = threadIdx.x; i < DM; i += 256) h[i] = x[i] * inv * w[i];
}

// ---------------------------------------------------------------------------
// Generic SGEMM: C[m,n] = sum_k A[m*lda+k] * W[n*K+k]   (+ optional bias/softplus)
// BM=BN=128, BK=16, 256 threads, 8x8 per thread
// ---------------------------------------------------------------------------
#define BM 128
#define BN 128
#define BKK 16

__global__ __launch_bounds__(256)
void k_gemm(int aBuf, int lda,
            const float* __restrict__ W0, const float* __restrict__ W1,
            int cBuf, int M, int N, int K,
            const float* __restrict__ bias0, const float* __restrict__ bias1,
            int epi) {
    int dir = blockIdx.z;
    const float* A = getbuf(aBuf, dir);
    float* C = getbuf(cBuf, dir);
    const float* W = dir ? W1 : W0;
    const float* bias = dir ? bias1 : bias0;

    __shared__ float As[BKK][BM];
    __shared__ float Ws[BKK][BN];

    int m0 = blockIdx.y * BM;
    int n0 = blockIdx.x * BN;
    int tid = threadIdx.x;
    int trow = tid >> 4;       // 0..15
    int tcol = tid & 15;       // 0..15

    float acc[8][8];
    #pragma unroll
    for (int i = 0; i < 8; i++)
        #pragma unroll
        for (int j = 0; j < 8; j++) acc[i][j] = 0.f;

    for (int k0 = 0; k0 < K; k0 += BKK) {
        #pragma unroll
        for (int t = 0; t < 2; t++) {
            int e = tid + t*256;
            int row = e >> 2;
            int kq = (e & 3) << 2;
            int gm = m0 + row;
            float4 v = make_float4(0.f,0.f,0.f,0.f);
            if (gm < M) v = *(const float4*)(A + (size_t)gm*lda + k0 + kq);
            As[kq+0][row]=v.x; As[kq+1][row]=v.y; As[kq+2][row]=v.z; As[kq+3][row]=v.w;
        }
        #pragma unroll
        for (int t = 0; t < 2; t++) {
            int e = tid + t*256;
            int row = e >> 2;
            int kq = (e & 3) << 2;
            int gn = n0 + row;
            float4 v = make_float4(0.f,0.f,0.f,0.f);
            if (gn < N) v = *(const float4*)(W + (size_t)gn*K + k0 + kq);
            Ws[kq+0][row]=v.x; Ws[kq+1][row]=v.y; Ws[kq+2][row]=v.z; Ws[kq+3][row]=v.w;
        }
        __syncthreads();
        #pragma unroll
        for (int kk = 0; kk < BKK; kk++) {
            float a[8], bq[8];
            #pragma unroll
            for (int i = 0; i < 8; i++) a[i] = As[kk][trow*8 + i];
            #pragma unroll
            for (int j = 0; j < 8; j++) bq[j] = Ws[kk][tcol*8 + j];
            #pragma unroll
            for (int i = 0; i < 8; i++)
                #pragma unroll
                for (int j = 0; j < 8; j++) acc[i][j] += a[i]*bq[j];
        }
        __syncthreads();
    }

    #pragma unroll
    for (int i = 0; i < 8; i++) {
        int m = m0 + trow*8 + i;
        if (m >= M) continue;
        #pragma unroll
        for (int j = 0; j < 8; j++) {
            int n = n0 + tcol*8 + j;
            if (n >= N) continue;
            float v = acc[i][j];
            if (epi == 1) {
                v += bias[n];
                v = (v > 20.f) ? v : log1pf(__expf(v));   // softplus
            }
            C[(size_t)m*N + n] = v;
        }
    }
}

// ---------------------------------------------------------------------------
// Causal depthwise conv1d (k=4) + bias + SiLU     xs = g_xz[..., :DI]
// ---------------------------------------------------------------------------
__global__ void k_conv(const float* __restrict__ cwF, const float* __restrict__ cwB,
                       const float* __restrict__ cbF, const float* __restrict__ cbB) {
    int idx = blockIdx.x * blockDim.x + threadIdx.x;   // over RWS*DI
    int dir = blockIdx.y;
    if (idx >= RWS*DI) return;
    int row = idx / DI, c = idx % DI;
    int b = row / LSEQ, l = row % LSEQ;
    const float* cw = (dir ? cwB : cwF) + c*DC;
    float acc = (dir ? cbB : cbF)[c];
    const float* xz = g_xz[dir];
    #pragma unroll
    for (int k = 0; k < DC; k++) {
        int ls = l - (DC-1) + k;
        if (ls >= 0) acc += xz[((size_t)(b*LSEQ + ls))*2*DI + c] * cw[k];
    }
    g_xc[dir][idx] = acc / (1.f + __expf(-acc));       // silu
}

// ---------------------------------------------------------------------------
// Selective scan, fused with D-skip and silu(z) gating.
// One thread per channel d; B/C staged in smem per 64-step chunk.
// ---------------------------------------------------------------------------
#define SCAN_TD 128
#define TCH 64

__global__ __launch_bounds__(SCAN_TD)
void k_scan(const float* __restrict__ alF, const float* __restrict__ alB,
            const float* __restrict__ dpF, const float* __restrict__ dpB) {
    int dir = blockIdx.z;
    int b = blockIdx.y;
    int d = blockIdx.x * SCAN_TD + threadIdx.x;

    const float* Alog = (dir ? alB : alF) + (size_t)d * DS;
    float Arow[DS];
    #pragma unroll
    for (int n = 0; n < DS; n++) Arow[n] = -__expf(Alog[n]);
    float Dv = (dir ? dpB : dpF)[d];

    float h[DS];
    #pragma unroll
    for (int n = 0; n < DS; n++) h[n] = 0.f;

    __shared__ float sB[TCH][DS];
    __shared__ float sC[TCH][DS];

    const float* dbl   = g_dbl[dir];
    const float* delt  = g_delta[dir];
    const float* xcb   = g_xc[dir];
    const float* xzb   = g_xz[dir];
    float* yb          = g_y[dir];

    for (int t0 = 0; t0 < LSEQ; t0 += TCH) {
        for (int i = threadIdx.x; i < TCH*DS; i += SCAN_TD) {
            int tt = i / DS, n = i % DS;
            size_t r = (size_t)(b*LSEQ + t0 + tt);
            sB[tt][n] = dbl[r*DBLW + DTR + n];
            sC[tt][n] = dbl[r*DBLW + DTR + DS + n];
        }
        __syncthreads();
        for (int tt = 0; tt < TCH; tt++) {
            size_t r = (size_t)(b*LSEQ + t0 + tt);
            float dv = delt[r*DI + d];
            float xv = xcb[r*DI + d];
            float du = dv * xv;
            float y = 0.f;
            #pragma unroll
            for (int n = 0; n < DS; n++) {
                float e = __expf(dv * Arow[n]);
                h[n] = h[n]*e + du*sB[tt][n];
                y += h[n]*sC[tt][n];
            }
            float zv = xzb[r*2*DI + DI + d];
            yb[r*DI + d] = (y + xv*Dv) * (zv / (1.f + __expf(-zv)));
        }
        __syncthreads();
    }
}

// ---------------------------------------------------------------------------
// Copy layer output (g_x) into d_out[layer, b, l, dir*DM : dir*DM+DM]
// ---------------------------------------------------------------------------
__global__ void k_copyout(float* __restrict__ out, int layer) {
    int idx4 = blockIdx.x * blockDim.x + threadIdx.x;   // over RWS*DM/4
    int dir = blockIdx.y;
    if (idx4 >= RWS*DM/4) return;
    int row = idx4 / (DM/4);
    int n4  = idx4 % (DM/4);
    float4 v = ((const float4*)(g_x[dir]))[idx4];
    size_t dst = ((size_t)layer*RWS + row) * (2*DM) + dir*DM + n4*4;
    *(float4*)(out + dst) = v;
}

// ---------------------------------------------------------------------------
// Host launcher
// ---------------------------------------------------------------------------
extern "C" void kernel_launch(void* const* d_in, const int* in_sizes, int n_in,
                              void* d_out, int out_size) {
    (void)in_sizes; (void)n_in; (void)out_size;
    const int* ids = (const int*)d_in[0];
    const float* F[11]; const float* Bw[11];
    for (int i = 0; i < 11; i++) {
        F[i]  = (const float*)d_in[1 + i];
        Bw[i] = (const float*)d_in[12 + i];
    }
    float* out = (float*)d_out;

    k_embed<<<dim3(RWS, 2), 192>>>(ids, F[0], Bw[0]);

    for (int layer = 0; layer < NL; layer++) {
        const float* nwF = F[1]  + (size_t)layer*DM;
        const float* nwB = Bw[1] + (size_t)layer*DM;
        const float* ipF = F[2]  + (size_t)layer*2*DI*DM;
        const float* ipB = Bw[2] + (size_t)layer*2*DI*DM;
        const float* cwF = F[3]  + (size_t)layer*DI*DC;
        const float* cwB = Bw[3] + (size_t)layer*DI*DC;
        const float* cbF = F[4]  + (size_t)layer*DI;
        const float* cbB = Bw[4] + (size_t)layer*DI;
        const float* xpF = F[5]  + (size_t)layer*DBLW*DI;
        const float* xpB = Bw[5] + (size_t)layer*DBLW*DI;
        const float* dwF = F[6]  + (size_t)layer*DI*DTR;
        const float* dwB = Bw[6] + (size_t)layer*DI*DTR;
        const float* dbF = F[7]  + (size_t)layer*DI;
        const float* dbB = Bw[7] + (size_t)layer*DI;
        const float* alF = F[8]  + (size_t)layer*DI*DS;
        const float* alB = Bw[8] + (size_t)layer*DI*DS;
        const float* dpF = F[9]  + (size_t)layer*DI;
        const float* dpB = Bw[9] + (size_t)layer*DI;
        const float* opF = F[10] + (size_t)layer*DM*DI;
        const float* opB = Bw[10]+ (size_t)layer*DM*DI;

        // 1. RMSNorm: g_x -> g_h
        k_rmsnorm<<<dim3(RWS, 2), 256>>>(nwF, nwB);

        // 2. in_proj: g_h [2048x768] @ W[3072x768]^T -> g_xz [2048x3072]
        k_gemm<<<dim3(2*DI/BN, RWS/BM, 2), 256>>>(
            0, DM, ipF, ipB, 1, RWS, 2*DI, DM, nullptr, nullptr, 0);

        // 3. conv1d + silu: g_xz[:, :DI] -> g_xc
        k_conv<<<dim3(RWS*DI/256, 2), 256>>>(cwF, cwB, cbF, cbB);

        // 4. x_proj: g_xc [2048x1536] @ W[80x1536]^T -> g_dbl [2048x80]
        k_gemm<<<dim3(1, RWS/BM, 2), 256>>>(
            2, DI, xpF, xpB, 3, RWS, DBLW, DI, nullptr, nullptr, 0);

        // 5. delta: softplus(g_dbl[:, :48] @ dt_w^T + dt_b) -> g_delta [2048x1536]
        k_gemm<<<dim3(DI/BN, RWS/BM, 2), 256>>>(
            3, DBLW, dwF, dwB, 4, RWS, DI, DTR, dbF, dbB, 1);

        // 6. selective scan + D-skip + silu(z) gating -> g_y
        k_scan<<<dim3(DI/SCAN_TD, BSZ, 2), SCAN_TD>>>(alF, alB, dpF, dpB);

        // 7. out_proj: g_y [2048x1536] @ W[768x1536]^T -> g_x (next layer input)
        k_gemm<<<dim3(DM/BN, RWS/BM, 2), 256>>>(
            5, DI, opF, opB, 6, RWS, DM, DI, nullptr, nullptr, 0);

        // 8. write this layer's output slice
        k_copyout<<<dim3(RWS*DM/4/256, 2), 256>>>(out, layer);
    }
}

// round 4
// speedup vs baseline: 1.6017x; 1.6017x over previous
#include <cuda_runtime.h>
#include <cuda_bf16.h>
#include <cstdint>

#define BSZ 2
#define LSEQ 1024
#define DM 768
#define DI 1536
#define DS 16
#define DC 4
#define DTR 48
#define NL 24
#define RWS (BSZ*LSEQ)
#define DBLW (DTR + 2*DS)       /* 80 */
#define EPSF 1e-5f

// ---------------------------------------------------------------------------
// Scratch
// ---------------------------------------------------------------------------
__device__ float g_x[2][RWS*DM];
__device__ float g_h[2][RWS*DM];
__device__ float g_xz[2][RWS*2*DI];
__device__ float g_xc[2][RWS*DI];
__device__ float g_dbl[2][RWS*DBLW];
__device__ float g_delta[2][RWS*DI];
__device__ float g_y[2][RWS*DI];

__device__ __forceinline__ float* getbuf(int w, int dir) {
    switch (w) {
        case 0: return g_h[dir];
        case 1: return g_xz[dir];
        case 2: return g_xc[dir];
        case 3: return g_dbl[dir];
        case 4: return g_delta[dir];
        case 5: return g_y[dir];
        default: return g_x[dir];
    }
}

__device__ __forceinline__ uint32_t smem_u32(const void* p) {
    uint32_t a;
    asm("{ .reg .u64 t; cvta.to.shared.u64 t, %1; cvt.u32.u64 %0, t; }" : "=r"(a) : "l"(p));
    return a;
}

#define LDSM4(r, addr) \
    asm volatile("ldmatrix.sync.aligned.m8n8.x4.shared.b16 {%0,%1,%2,%3}, [%4];" \
        : "=r"((r)[0]), "=r"((r)[1]), "=r"((r)[2]), "=r"((r)[3]) : "r"(addr))

#define MMA16816(c, a, b0v, b1v) \
    asm volatile("mma.sync.aligned.m16n8k16.row.col.f32.bf16.bf16.f32 " \
        "{%0,%1,%2,%3}, {%4,%5,%6,%7}, {%8,%9}, {%0,%1,%2,%3};" \
        : "+f"((c)[0]), "+f"((c)[1]), "+f"((c)[2]), "+f"((c)[3]) \
        : "r"((a)[0]), "r"((a)[1]), "r"((a)[2]), "r"((a)[3]), "r"(b0v), "r"(b1v))

// ---------------------------------------------------------------------------
// Embedding (+ flip for backward stack)
// ---------------------------------------------------------------------------
__global__ void k_embed(const int* __restrict__ ids,
                        const float* __restrict__ embF,
                        const float* __restrict__ embB) {
    int row = blockIdx.x, dir = blockIdx.y;
    int b = row / LSEQ, l = row % LSEQ;
    int tok = (dir == 0) ? ids[b*LSEQ + l] : ids[b*LSEQ + (LSEQ-1-l)];
    const float* emb = (dir == 0) ? embF : embB;
    const float4* src = (const float4*)(emb + (size_t)tok * DM);
    float4* dst = (float4*)(g_x[dir] + (size_t)row * DM);
    for (int i = threadIdx.x; i < DM/4; i += blockDim.x) dst[i] = src[i];
}

// ---------------------------------------------------------------------------
// RMSNorm
// ---------------------------------------------------------------------------
__global__ void k_rmsnorm(const float* __restrict__ wF, const float* __restrict__ wB) {
    int row = blockIdx.x, dir = blockIdx.y;
    const float* x = g_x[dir] + (size_t)row * DM;
    float* h = g_h[dir] + (size_t)row * DM;
    const float* w = dir ? wB : wF;
    float s = 0.f;
    for (int i = threadIdx.x; i < DM; i += 256) { float v = x[i]; s += v*v; }
    #pragma unroll
    for (int o = 16; o; o >>= 1) s += __shfl_down_sync(0xffffffffu, s, o);
    __shared__ float red[8];
    if ((threadIdx.x & 31) == 0) red[threadIdx.x >> 5] = s;
    __syncthreads();
    if (threadIdx.x < 8) {
        float t = red[threadIdx.x];
        #pragma unroll
        for (int o = 4; o; o >>= 1) t += __shfl_down_sync(0xffu, t, o);
        if (threadIdx.x == 0) red[0] = t;
    }
    __syncthreads();
    float inv = rsqrtf(red[0] / (float)DM + EPSF);
    for (int i = threadIdx.x; i < DM; i += 256) h[i] = x[i] * inv * w[i];
}

// ---------------------------------------------------------------------------
// Split-bf16 HMMA GEMM: C[m,n] = sum_k A[m,k]*W[n,k]   (fp32 in/out)
// CTA tile 128x128, K chunks of 64, 8 warps (4 along M x 2 along N),
// warp tile 32x64, mma.m16n8k16 with 3-product hi/lo decomposition.
// smem tiles: AHI/ALO/BHI/BLO, each 128 rows x 128B (SW128 swizzle).
// ---------------------------------------------------------------------------
#define GTK 64
#define TILE_B 16384
#define GEMM_SMEM (4*TILE_B)

__global__ __launch_bounds__(256)
void k_gemm(int aBuf, int lda,
            const float* __restrict__ W0, const float* __restrict__ W1,
            int cBuf, int M, int N, int K,
            const float* __restrict__ b0, const float* __restrict__ b1,
            int epi) {
    extern __shared__ __align__(1024) char smem[];
    const int dir = blockIdx.z;
    const float* A = getbuf(aBuf, dir);
    float* C = getbuf(cBuf, dir);
    const float* W = dir ? W1 : W0;
    const float* bias = dir ? b1 : b0;

    const uint32_t tb = smem_u32(smem);
    const uint32_t AHI = tb, ALO = tb + TILE_B, BHI = tb + 2*TILE_B, BLO = tb + 3*TILE_B;

    const int tid = threadIdx.x;
    const int lane = tid & 31, wid = tid >> 5;
    const int wm = wid & 3, wn = wid >> 2;
    const int m0 = blockIdx.y * 128, n0 = blockIdx.x * 128;

    // ldmatrix lane addressing.  SW128: addr = row*128 + (byte ^ ((row&7)<<4))
    const int l15 = lane & 15;
    const int a_kbx = (lane & 16) ? 16 : 0;          // lanes 16-31 -> k8-15 (byte +16)
    const int b_nrow = (lane & 7) + ((lane & 16) ? 8 : 0);
    const int b_kbx = (lane & 8) ? 16 : 0;

    uint32_t aOff[2], aMsk[2];
    #pragma unroll
    for (int mt = 0; mt < 2; mt++) {
        int r = wm*32 + mt*16 + l15;
        aOff[mt] = r * 128;
        aMsk[mt] = (r & 7) << 4;
    }
    // 4 B ldmatrix groups of n-width 16 -> warp n-extent 64
    uint32_t bOff[4], bMsk[4];
    #pragma unroll
    for (int g = 0; g < 4; g++) {
        int r = wn*64 + g*16 + b_nrow;
        bOff[g] = r * 128;
        bMsk[g] = (r & 7) << 4;
    }

    float c[2][8][4];
    #pragma unroll
    for (int i = 0; i < 2; i++)
        #pragma unroll
        for (int j = 0; j < 8; j++)
            #pragma unroll
            for (int q = 0; q < 4; q++) c[i][j][q] = 0.f;

    const int nchunks = (K + GTK - 1) / GTK;
    for (int ch = 0; ch < nchunks; ch++) {
        int k0 = ch * GTK;
        // ---- stage A: 128 rows x 64 fp32 -> bf16 hi/lo in smem ----
        #pragma unroll
        for (int i = 0; i < 8; i++) {
            int idx = tid + i*256;
            int row = idx >> 4, c4 = idx & 15;
            int kk = k0 + c4*4;
            float4 v = make_float4(0.f,0.f,0.f,0.f);
            if (kk < K) v = *(const float4*)(A + (size_t)(m0+row)*lda + kk);
            __nv_bfloat162 h01 = __floats2bfloat162_rn(v.x, v.y);
            __nv_bfloat162 h23 = __floats2bfloat162_rn(v.z, v.w);
            __nv_bfloat162 l01 = __floats2bfloat162_rn(v.x - __bfloat162float(h01.x),
                                                       v.y - __bfloat162float(h01.y));
            __nv_bfloat162 l23 = __floats2bfloat162_rn(v.z - __bfloat162float(h23.x),
                                                       v.w - __bfloat162float(h23.y));
            uint32_t off = row*128 + c4*8;
            uint32_t sw = off ^ ((off >> 3) & 0x70);
            *(uint2*)(smem + (AHI - tb) + sw) = make_uint2(*(uint32_t*)&h01, *(uint32_t*)&h23);
            *(uint2*)(smem + (ALO - tb) + sw) = make_uint2(*(uint32_t*)&l01, *(uint32_t*)&l23);
        }
        // ---- stage B (weights, [N,K] row-major; guard n<N) ----
        #pragma unroll
        for (int i = 0; i < 8; i++) {
            int idx = tid + i*256;
            int row = idx >> 4, c4 = idx & 15;
            int kk = k0 + c4*4;
            int gn = n0 + row;
            float4 v = make_float4(0.f,0.f,0.f,0.f);
            if (gn < N && kk < K) v = *(const float4*)(W + (size_t)gn*K + kk);
            __nv_bfloat162 h01 = __floats2bfloat162_rn(v.x, v.y);
            __nv_bfloat162 h23 = __floats2bfloat162_rn(v.z, v.w);
            __nv_bfloat162 l01 = __floats2bfloat162_rn(v.x - __bfloat162float(h01.x),
                                                       v.y - __bfloat162float(h01.y));
            __nv_bfloat162 l23 = __floats2bfloat162_rn(v.z - __bfloat162float(h23.x),
                                                       v.w - __bfloat162float(h23.y));
            uint32_t off = row*128 + c4*8;
            uint32_t sw = off ^ ((off >> 3) & 0x70);
            *(uint2*)(smem + (BHI - tb) + sw) = make_uint2(*(uint32_t*)&h01, *(uint32_t*)&h23);
            *(uint2*)(smem + (BLO - tb) + sw) = make_uint2(*(uint32_t*)&l01, *(uint32_t*)&l23);
        }
        __syncthreads();

        // ---- compute: 4 k16 steps ----
        #pragma unroll
        for (int ks = 0; ks < 4; ks++) {
            const int kb = ks * 32;
            uint32_t ah[2][4], al[2][4];
            #pragma unroll
            for (int mt = 0; mt < 2; mt++) {
                uint32_t kx = (uint32_t)(kb + a_kbx) ^ aMsk[mt];
                LDSM4(ah[mt], AHI + aOff[mt] + kx);
                LDSM4(al[mt], ALO + aOff[mt] + kx);
            }
            // B in two 32-wide halves to bound register pressure
            #pragma unroll
            for (int h2 = 0; h2 < 2; h2++) {
                uint32_t bh[2][4], bl[2][4];
                #pragma unroll
                for (int g = 0; g < 2; g++) {
                    uint32_t kx = (uint32_t)(kb + b_kbx) ^ bMsk[h2*2 + g];
                    LDSM4(bh[g], BHI + bOff[h2*2 + g] + kx);
                    LDSM4(bl[g], BLO + bOff[h2*2 + g] + kx);
                }
                #pragma unroll
                for (int mt = 0; mt < 2; mt++)
                    #pragma unroll
                    for (int nt = 0; nt < 4; nt++) {
                        int g = nt >> 1, o = (nt & 1) * 2;
                        float* cc = c[mt][h2*4 + nt];
                        MMA16816(cc, ah[mt], bh[g][o], bh[g][o+1]);
                        MMA16816(cc, ah[mt], bl[g][o], bl[g][o+1]);
                        MMA16816(cc, al[mt], bh[g][o], bh[g][o+1]);
                    }
            }
        }
        __syncthreads();
    }

    // ---- epilogue ----
    const int mrow = m0 + wm*32 + (lane >> 2);
    const int ncol0 = n0 + wn*64 + (lane & 3)*2;
    #pragma unroll
    for (int mt = 0; mt < 2; mt++) {
        #pragma unroll
        for (int nt = 0; nt < 8; nt++) {
            int n = ncol0 + nt*8;
            if (n >= N) continue;
            #pragma unroll
            for (int half = 0; half < 2; half++) {
                int m = mrow + mt*16 + half*8;
                float v0 = c[mt][nt][half*2+0];
                float v1 = c[mt][nt][half*2+1];
                if (epi == 1) {
                    v0 += bias[n];   v1 += bias[n+1];
                    v0 = (v0 > 20.f) ? v0 : log1pf(__expf(v0));
                    v1 = (v1 > 20.f) ? v1 : log1pf(__expf(v1));
                }
                *(float2*)(C + (size_t)m*N + n) = make_float2(v0, v1);
            }
        }
    }
}

// ---------------------------------------------------------------------------
// Causal depthwise conv1d (k=4) + bias + SiLU
// ---------------------------------------------------------------------------
__global__ void k_conv(const float* __restrict__ cwF, const float* __restrict__ cwB,
                       const float* __restrict__ cbF, const float* __restrict__ cbB) {
    int idx = blockIdx.x * blockDim.x + threadIdx.x;
    int dir = blockIdx.y;
    if (idx >= RWS*DI) return;
    int row = idx / DI, c = idx % DI;
    int b = row / LSEQ, l = row % LSEQ;
    const float* cw = (dir ? cwB : cwF) + c*DC;
    float acc = (dir ? cbB : cbF)[c];
    const float* xz = g_xz[dir];
    #pragma unroll
    for (int k = 0; k < DC; k++) {
        int ls = l - (DC-1) + k;
        if (ls >= 0) acc += xz[((size_t)(b*LSEQ + ls))*2*DI + c] * cw[k];
    }
    g_xc[dir][idx] = acc / (1.f + __expf(-acc));
}

// ---------------------------------------------------------------------------
// Selective scan + D-skip + silu(z) gating.  Fast path when A[n] == -(n+1).
// ---------------------------------------------------------------------------
#define SCAN_TD 128
#define TCH 64

__global__ __launch_bounds__(SCAN_TD)
void k_scan(const float* __restrict__ alF, const float* __restrict__ alB,
            const float* __restrict__ dpF, const float* __restrict__ dpB) {
    int dir = blockIdx.z;
    int b = blockIdx.y;
    int d = blockIdx.x * SCAN_TD + threadIdx.x;

    const float* Alog = (dir ? alB : alF) + (size_t)d * DS;
    float Arow[DS];
    bool fastA = true;
    #pragma unroll
    for (int n = 0; n < DS; n++) {
        Arow[n] = -__expf(Alog[n]);
        float tgt = -(float)(n+1);
        fastA = fastA && (fabsf(Arow[n] - tgt) <= 1e-4f * (float)(n+1));
    }
    float Dv = (dir ? dpB : dpF)[d];

    float h[DS];
    #pragma unroll
    for (int n = 0; n < DS; n++) h[n] = 0.f;

    __shared__ float sB[TCH][DS];
    __shared__ float sC[TCH][DS];

    const float* dbl  = g_dbl[dir];
    const float* delt = g_delta[dir];
    const float* xcb  = g_xc[dir];
    const float* xzb  = g_xz[dir];
    float* yb         = g_y[dir];

    for (int t0 = 0; t0 < LSEQ; t0 += TCH) {
        for (int i = threadIdx.x; i < TCH*DS; i += SCAN_TD) {
            int tt = i / DS, n = i % DS;
            size_t r = (size_t)(b*LSEQ + t0 + tt);
            sB[tt][n] = dbl[r*DBLW + DTR + n];
            sC[tt][n] = dbl[r*DBLW + DTR + DS + n];
        }
        __syncthreads();
        if (fastA) {
            for (int tt = 0; tt < TCH; tt++) {
                size_t r = (size_t)(b*LSEQ + t0 + tt);
                float dv = delt[r*DI + d];
                float xv = xcb[r*DI + d];
                float du = dv * xv;
                float e1 = __expf(-dv);
                float p = e1;
                float y = 0.f;
                #pragma unroll
                for (int n = 0; n < DS; n++) {
                    h[n] = h[n]*p + du*sB[tt][n];
                    y += h[n]*sC[tt][n];
                    p *= e1;
                }
                float zv = xzb[r*2*DI + DI + d];
                yb[r*DI + d] = (y + xv*Dv) * (zv / (1.f + __expf(-zv)));
            }
        } else {
            for (int tt = 0; tt < TCH; tt++) {
                size_t r = (size_t)(b*LSEQ + t0 + tt);
                float dv = delt[r*DI + d];
                float xv = xcb[r*DI + d];
                float du = dv * xv;
                float y = 0.f;
                #pragma unroll
                for (int n = 0; n < DS; n++) {
                    float e = __expf(dv * Arow[n]);
                    h[n] = h[n]*e + du*sB[tt][n];
                    y += h[n]*sC[tt][n];
                }
                float zv = xzb[r*2*DI + DI + d];
                yb[r*DI + d] = (y + xv*Dv) * (zv / (1.f + __expf(-zv)));
            }
        }
        __syncthreads();
    }
}

// ---------------------------------------------------------------------------
// Copy layer output into d_out[layer, b, l, dir*DM:...]
// ---------------------------------------------------------------------------
__global__ void k_copyout(float* __restrict__ out, int layer) {
    int idx4 = blockIdx.x * blockDim.x + threadIdx.x;
    int dir = blockIdx.y;
    if (idx4 >= RWS*DM/4) return;
    int row = idx4 / (DM/4);
    int n4  = idx4 % (DM/4);
    float4 v = ((const float4*)(g_x[dir]))[idx4];
    size_t dst = ((size_t)layer*RWS + row) * (2*DM) + dir*DM + n4*4;
    *(float4*)(out + dst) = v;
}

// ---------------------------------------------------------------------------
// Host launcher
// ---------------------------------------------------------------------------
extern "C" void kernel_launch(void* const* d_in, const int* in_sizes, int n_in,
                              void* d_out, int out_size) {
    (void)in_sizes; (void)n_in; (void)out_size;
    const int* ids = (const int*)d_in[0];
    const float* F[11]; const float* Bw[11];
    for (int i = 0; i < 11; i++) {
        F[i]  = (const float*)d_in[1 + i];
        Bw[i] = (const float*)d_in[12 + i];
    }
    float* out = (float*)d_out;

    static int smem_set = 0;
    if (!smem_set) {
        cudaFuncSetAttribute(k_gemm, cudaFuncAttributeMaxDynamicSharedMemorySize, GEMM_SMEM);
        smem_set = 1;
    }

    k_embed<<<dim3(RWS, 2), 192>>>(ids, F[0], Bw[0]);

    for (int layer = 0; layer < NL; layer++) {
        const float* nwF = F[1]  + (size_t)layer*DM;
        const float* nwB = Bw[1] + (size_t)layer*DM;
        const float* ipF = F[2]  + (size_t)layer*2*DI*DM;
        const float* ipB = Bw[2] + (size_t)layer*2*DI*DM;
        const float* cwF = F[3]  + (size_t)layer*DI*DC;
        const float* cwB = Bw[3] + (size_t)layer*DI*DC;
        const float* cbF = F[4]  + (size_t)layer*DI;
        const float* cbB = Bw[4] + (size_t)layer*DI;
        const float* xpF = F[5]  + (size_t)layer*DBLW*DI;
        const float* xpB = Bw[5] + (size_t)layer*DBLW*DI;
        const float* dwF = F[6]  + (size_t)layer*DI*DTR;
        const float* dwB = Bw[6] + (size_t)layer*DI*DTR;
        const float* dbF = F[7]  + (size_t)layer*DI;
        const float* dbB = Bw[7] + (size_t)layer*DI;
        const float* alF = F[8]  + (size_t)layer*DI*DS;
        const float* alB = Bw[8] + (size_t)layer*DI*DS;
        const float* dpF = F[9]  + (size_t)layer*DI;
        const float* dpB = Bw[9] + (size_t)layer*DI;
        const float* opF = F[10] + (size_t)layer*DM*DI;
        const float* opB = Bw[10]+ (size_t)layer*DM*DI;

        k_rmsnorm<<<dim3(RWS, 2), 256>>>(nwF, nwB);

        // in_proj: [2048x768] @ [3072x768]^T -> g_xz
        k_gemm<<<dim3(2*DI/128, RWS/128, 2), 256, GEMM_SMEM>>>(
            0, DM, ipF, ipB, 1, RWS, 2*DI, DM, nullptr, nullptr, 0);

        k_conv<<<dim3(RWS*DI/256, 2), 256>>>(cwF, cwB, cbF, cbB);

        // x_proj: [2048x1536] @ [80x1536]^T -> g_dbl
        k_gemm<<<dim3(1, RWS/128, 2), 256, GEMM_SMEM>>>(
            2, DI, xpF, xpB, 3, RWS, DBLW, DI, nullptr, nullptr, 0);

        // delta: softplus([2048x80(:48)] @ [1536x48]^T + dt_b) -> g_delta
        k_gemm<<<dim3(DI/128, RWS/128, 2), 256, GEMM_SMEM>>>(
            3, DBLW, dwF, dwB, 4, RWS, DI, DTR, dbF, dbB, 1);

        k_scan<<<dim3(DI/SCAN_TD, BSZ, 2), SCAN_TD>>>(alF, alB, dpF, dpB);

        // out_proj: [2048x1536] @ [768x1536]^T -> g_x
        k_gemm<<<dim3(DM/128, RWS/128, 2), 256, GEMM_SMEM>>>(
            5, DI, opF, opB, 6, RWS, DM, DI, nullptr, nullptr, 0);

        k_copyout<<<dim3(RWS*DM/4/256, 2), 256>>>(out, layer);
    }
}

// round 5
// speedup vs baseline: 1.6550x; 1.0333x over previous
#include <cuda_runtime.h>
#include <cuda_bf16.h>
#include <cstdint>

#define BSZ 2
#define LSEQ 1024
#define DM 768
#define DI 1536
#define DS 16
#define DC 4
#define DTR 48
#define NL 24
#define RWS (BSZ*LSEQ)
#define DBLW (DTR + 2*DS)       /* 80 */
#define EPSF 1e-5f

typedef __nv_bfloat16 bf16;
typedef __nv_bfloat162 bf162;

// ---------------------------------------------------------------------------
// Scratch (f32 activations)
// ---------------------------------------------------------------------------
__device__ float g_x[2][RWS*DM];        // layer input / out_proj output
__device__ float g_xz[2][RWS*2*DI];     // in_proj output (xs | z)
__device__ float g_xc[2][RWS*DI];       // conv+silu output (scan reads)
__device__ float g_dbl[2][RWS*DBLW];    // x_proj output (scan reads B,C)
__device__ float g_delta[2][RWS*DI];    // softplus(...)

// bf16 hi/lo activations (GEMM A inputs)
__device__ bf16 g_h_hi[2][RWS*DM],   g_h_lo[2][RWS*DM];
__device__ bf16 g_xc_hi[2][RWS*DI],  g_xc_lo[2][RWS*DI];
__device__ bf16 g_dbl_hi[2][RWS*DBLW], g_dbl_lo[2][RWS*DBLW];
__device__ bf16 g_y_hi[2][RWS*DI],   g_y_lo[2][RWS*DI];

// bf16 hi/lo weights (split once per call)
__device__ bf16 g_wip_hi[2][NL*2*DI*DM], g_wip_lo[2][NL*2*DI*DM];
__device__ bf16 g_wxp_hi[2][NL*DBLW*DI], g_wxp_lo[2][NL*DBLW*DI];
__device__ bf16 g_wdt_hi[2][NL*DI*DTR],  g_wdt_lo[2][NL*DI*DTR];
__device__ bf16 g_wop_hi[2][NL*DM*DI],   g_wop_lo[2][NL*DM*DI];

__device__ __forceinline__ float* getCf(int w, int dir) {
    switch (w) {
        case 1: return g_xz[dir];
        case 3: return g_dbl[dir];
        case 4: return g_delta[dir];
        default: return g_x[dir];
    }
}

__device__ __forceinline__ uint32_t smem_u32(const void* p) {
    uint32_t a;
    asm("{ .reg .u64 t; cvta.to.shared.u64 t, %1; cvt.u32.u64 %0, t; }" : "=r"(a) : "l"(p));
    return a;
}

__device__ __forceinline__ void fsplit(float v, bf16* hp, bf16* lp) {
    bf16 h = __float2bfloat16_rn(v);
    *hp = h;
    *lp = __float2bfloat16_rn(v - __bfloat162float(h));
}

#define CP16(dst, src, sz) \
    asm volatile("cp.async.cg.shared.global [%0], [%1], 16, %2;" \
        :: "r"(dst), "l"(src), "r"(sz) : "memory")
#define CP_COMMIT() asm volatile("cp.async.commit_group;" ::: "memory")
#define CP_WAIT1()  asm volatile("cp.async.wait_group 1;" ::: "memory")
#define CP_WAIT0()  asm volatile("cp.async.wait_group 0;" ::: "memory")

#define LDSM4(r, addr) \
    asm volatile("ldmatrix.sync.aligned.m8n8.x4.shared.b16 {%0,%1,%2,%3}, [%4];" \
        : "=r"((r)[0]), "=r"((r)[1]), "=r"((r)[2]), "=r"((r)[3]) : "r"(addr))

#define MMA16816(c, a, b0v, b1v) \
    asm volatile("mma.sync.aligned.m16n8k16.row.col.f32.bf16.bf16.f32 " \
        "{%0,%1,%2,%3}, {%4,%5,%6,%7}, {%8,%9}, {%0,%1,%2,%3};" \
        : "+f"((c)[0]), "+f"((c)[1]), "+f"((c)[2]), "+f"((c)[3]) \
        : "r"((a)[0]), "r"((a)[1]), "r"((a)[2]), "r"((a)[3]), "r"(b0v), "r"(b1v))

// ---------------------------------------------------------------------------
// Weight split: f32 -> bf16 hi/lo
// ---------------------------------------------------------------------------
__global__ void k_wsplit(const float4* __restrict__ src,
                         bf162* __restrict__ hi, bf162* __restrict__ lo, int n4) {
    int i = blockIdx.x * blockDim.x + threadIdx.x;
    if (i >= n4) return;
    float4 v = src[i];
    bf162 h01 = __floats2bfloat162_rn(v.x, v.y);
    bf162 h23 = __floats2bfloat162_rn(v.z, v.w);
    bf162 l01 = __floats2bfloat162_rn(v.x - __bfloat162float(h01.x),
                                      v.y - __bfloat162float(h01.y));
    bf162 l23 = __floats2bfloat162_rn(v.z - __bfloat162float(h23.x),
                                      v.w - __bfloat162float(h23.y));
    hi[i*2] = h01; hi[i*2+1] = h23;
    lo[i*2] = l01; lo[i*2+1] = l23;
}

// ---------------------------------------------------------------------------
// Embedding
// ---------------------------------------------------------------------------
__global__ void k_embed(const int* __restrict__ ids,
                        const float* __restrict__ embF,
                        const float* __restrict__ embB) {
    int row = blockIdx.x, dir = blockIdx.y;
    int b = row / LSEQ, l = row % LSEQ;
    int tok = (dir == 0) ? ids[b*LSEQ + l] : ids[b*LSEQ + (LSEQ-1-l)];
    const float* emb = (dir == 0) ? embF : embB;
    const float4* src = (const float4*)(emb + (size_t)tok * DM);
    float4* dst = (float4*)(g_x[dir] + (size_t)row * DM);
    for (int i = threadIdx.x; i < DM/4; i += blockDim.x) dst[i] = src[i];
}

// ---------------------------------------------------------------------------
// RMSNorm -> bf16 hi/lo
// ---------------------------------------------------------------------------
__global__ void k_rmsnorm(const float* __restrict__ wF, const float* __restrict__ wB) {
    int row = blockIdx.x, dir = blockIdx.y;
    const float* x = g_x[dir] + (size_t)row * DM;
    bf16* hh = g_h_hi[dir] + (size_t)row * DM;
    bf16* hl = g_h_lo[dir] + (size_t)row * DM;
    const float* w = dir ? wB : wF;
    float s = 0.f;
    for (int i = threadIdx.x; i < DM; i += 256) { float v = x[i]; s += v*v; }
    #pragma unroll
    for (int o = 16; o; o >>= 1) s += __shfl_down_sync(0xffffffffu, s, o);
    __shared__ float red[8];
    if ((threadIdx.x & 31) == 0) red[threadIdx.x >> 5] = s;
    __syncthreads();
    if (threadIdx.x < 8) {
        float t = red[threadIdx.x];
        #pragma unroll
        for (int o = 4; o; o >>= 1) t += __shfl_down_sync(0xffu, t, o);
        if (threadIdx.x == 0) red[0] = t;
    }
    __syncthreads();
    float inv = rsqrtf(red[0] / (float)DM + EPSF);
    for (int i = threadIdx.x; i < DM; i += 256) {
        float v = x[i] * inv * w[i];
        fsplit(v, hh + i, hl + i);
    }
}

// ---------------------------------------------------------------------------
// Split-bf16 HMMA GEMM, cp.async double-buffered.
// CTA tile 128x128, K chunks of 64, 8 warps (4 M x 2 N), warp tile 32x64.
// A/B pre-split bf16 hi/lo.  smem stage = AHI|ALO|BHI|BLO, 16KB each.
// ---------------------------------------------------------------------------
#define GTK 64
#define STAGE_B 65536
#define GEMM_SMEM (2*STAGE_B)

__device__ __forceinline__ void stage_tiles(
    uint32_t stg,
    const bf16* __restrict__ Ahi, const bf16* __restrict__ Alo,
    const bf16* __restrict__ Whi, const bf16* __restrict__ Wlo,
    int m0, int n0, int k0, int lda, int ldw, int N, int K, int tid)
{
    #pragma unroll
    for (int t = 0; t < 4; t++) {
        int idx = tid + t*256;
        int row = idx >> 3, col = idx & 7;
        int kk = k0 + col*8;
        uint32_t soff = (uint32_t)(row*128 + ((col*16) ^ ((row & 7) << 4)));
        int asz = (kk < K) ? 16 : 0;
        size_t aoffm = (size_t)(m0+row)*lda + (asz ? kk : 0);
        CP16(stg + soff,          Ahi + aoffm, asz);
        CP16(stg + 16384 + soff,  Alo + aoffm, asz);
        int gn = n0 + row;
        int bsz = (gn < N && kk < K) ? 16 : 0;
        size_t boff = (size_t)(bsz ? gn : 0)*ldw + (bsz ? kk : 0);
        CP16(stg + 32768 + soff,  Whi + boff, bsz);
        CP16(stg + 49152 + soff,  Wlo + boff, bsz);
    }
}

__global__ __launch_bounds__(256)
void k_gemm(int aId, int lda,
            const bf16* __restrict__ Whi0, const bf16* __restrict__ Wlo0,
            const bf16* __restrict__ Whi1, const bf16* __restrict__ Wlo1,
            int cfId, int cbfId, float* __restrict__ outp,
            int M, int N, int K,
            const float* __restrict__ b0, const float* __restrict__ b1,
            int epi) {
    extern __shared__ __align__(1024) char smem[];
    const int dir = blockIdx.z;
    const bf16 *Ahi, *Alo;
    switch (aId) {
        case 0: Ahi = g_h_hi[dir];   Alo = g_h_lo[dir];   break;
        case 1: Ahi = g_xc_hi[dir];  Alo = g_xc_lo[dir];  break;
        case 2: Ahi = g_dbl_hi[dir]; Alo = g_dbl_lo[dir]; break;
        default: Ahi = g_y_hi[dir];  Alo = g_y_lo[dir];   break;
    }
    const bf16* Whi = dir ? Whi1 : Whi0;
    const bf16* Wlo = dir ? Wlo1 : Wlo0;
    float* Cf = getCf(cfId, dir);
    bf16* Chi = (cbfId == 1) ? g_dbl_hi[dir] : nullptr;
    bf16* Clo = (cbfId == 1) ? g_dbl_lo[dir] : nullptr;
    const float* bias = dir ? b1 : b0;

    const uint32_t tb = smem_u32(smem);
    const int tid = threadIdx.x;
    const int lane = tid & 31, wid = tid >> 5;
    const int wm = wid & 3, wn = wid >> 2;
    const int m0 = blockIdx.y * 128, n0 = blockIdx.x * 128;

    // ldmatrix lane addressing (SW128: addr = row*128 + (byte ^ ((row&7)<<4)))
    const int l15 = lane & 15;
    const int a_kbx = (lane & 16) ? 16 : 0;
    const int b_nrow = (lane & 7) + ((lane & 16) ? 8 : 0);
    const int b_kbx = (lane & 8) ? 16 : 0;

    uint32_t aOff[2], aMsk[2];
    #pragma unroll
    for (int mt = 0; mt < 2; mt++) {
        int r = wm*32 + mt*16 + l15;
        aOff[mt] = r * 128;
        aMsk[mt] = (r & 7) << 4;
    }
    uint32_t bOff[4], bMsk[4];
    #pragma unroll
    for (int g = 0; g < 4; g++) {
        int r = wn*64 + g*16 + b_nrow;
        bOff[g] = r * 128;
        bMsk[g] = (r & 7) << 4;
    }

    float c[2][8][4];
    #pragma unroll
    for (int i = 0; i < 2; i++)
        #pragma unroll
        for (int j = 0; j < 8; j++)
            #pragma unroll
            for (int q = 0; q < 4; q++) c[i][j][q] = 0.f;

    const int nch = (K + GTK - 1) / GTK;
    stage_tiles(tb, Ahi, Alo, Whi, Wlo, m0, n0, 0, lda, K, N, K, tid);
    CP_COMMIT();

    for (int ch = 0; ch < nch; ch++) {
        if (ch + 1 < nch) {
            stage_tiles(tb + ((ch+1)&1)*STAGE_B, Ahi, Alo, Whi, Wlo,
                        m0, n0, (ch+1)*GTK, lda, K, N, K, tid);
            CP_COMMIT();
            CP_WAIT1();
        } else {
            CP_WAIT0();
        }
        __syncthreads();

        const uint32_t AHI = tb + (ch&1)*STAGE_B;
        const uint32_t ALO = AHI + 16384, BHI = AHI + 32768, BLO = AHI + 49152;
        #pragma unroll
        for (int ks = 0; ks < 4; ks++) {
            const int kb = ks * 32;
            uint32_t ah[2][4], al[2][4];
            #pragma unroll
            for (int mt = 0; mt < 2; mt++) {
                uint32_t kx = (uint32_t)(kb + a_kbx) ^ aMsk[mt];
                LDSM4(ah[mt], AHI + aOff[mt] + kx);
                LDSM4(al[mt], ALO + aOff[mt] + kx);
            }
            #pragma unroll
            for (int h2 = 0; h2 < 2; h2++) {
                uint32_t bh[2][4], bl[2][4];
                #pragma unroll
                for (int g = 0; g < 2; g++) {
                    uint32_t kx = (uint32_t)(kb + b_kbx) ^ bMsk[h2*2 + g];
                    LDSM4(bh[g], BHI + bOff[h2*2 + g] + kx);
                    LDSM4(bl[g], BLO + bOff[h2*2 + g] + kx);
                }
                #pragma unroll
                for (int mt = 0; mt < 2; mt++)
                    #pragma unroll
                    for (int nt = 0; nt < 4; nt++) {
                        int g = nt >> 1, o = (nt & 1) * 2;
                        float* cc = c[mt][h2*4 + nt];
                        MMA16816(cc, ah[mt], bh[g][o], bh[g][o+1]);
                        MMA16816(cc, ah[mt], bl[g][o], bl[g][o+1]);
                        MMA16816(cc, al[mt], bh[g][o], bh[g][o+1]);
                    }
            }
        }
        __syncthreads();
    }

    // ---- epilogue ----
    const int mrow = m0 + wm*32 + (lane >> 2);
    const int ncol0 = n0 + wn*64 + (lane & 3)*2;
    #pragma unroll
    for (int mt = 0; mt < 2; mt++) {
        #pragma unroll
        for (int nt = 0; nt < 8; nt++) {
            int n = ncol0 + nt*8;
            if (n >= N) continue;
            #pragma unroll
            for (int half = 0; half < 2; half++) {
                int m = mrow + mt*16 + half*8;
                float v0 = c[mt][nt][half*2+0];
                float v1 = c[mt][nt][half*2+1];
                if (epi == 1) {
                    v0 += bias[n];   v1 += bias[n+1];
                    v0 = (v0 > 20.f) ? v0 : log1pf(__expf(v0));
                    v1 = (v1 > 20.f) ? v1 : log1pf(__expf(v1));
                }
                *(float2*)(Cf + (size_t)m*N + n) = make_float2(v0, v1);
                if (Chi) {
                    fsplit(v0, Chi + (size_t)m*N + n,     Clo + (size_t)m*N + n);
                    fsplit(v1, Chi + (size_t)m*N + n + 1, Clo + (size_t)m*N + n + 1);
                }
                if (outp) {
                    *(float2*)(outp + (size_t)m*(2*DM) + dir*DM + n) = make_float2(v0, v1);
                }
            }
        }
    }
}

// ---------------------------------------------------------------------------
// Causal depthwise conv1d (k=4) + bias + SiLU -> f32 + bf16 hi/lo
// ---------------------------------------------------------------------------
__global__ void k_conv(const float* __restrict__ cwF, const float* __restrict__ cwB,
                       const float* __restrict__ cbF, const float* __restrict__ cbB) {
    int idx = blockIdx.x * blockDim.x + threadIdx.x;
    int dir = blockIdx.y;
    if (idx >= RWS*DI) return;
    int row = idx / DI, c = idx % DI;
    int b = row / LSEQ, l = row % LSEQ;
    const float* cw = (dir ? cwB : cwF) + c*DC;
    float acc = (dir ? cbB : cbF)[c];
    const float* xz = g_xz[dir];
    #pragma unroll
    for (int k = 0; k < DC; k++) {
        int ls = l - (DC-1) + k;
        if (ls >= 0) acc += xz[((size_t)(b*LSEQ + ls))*2*DI + c] * cw[k];
    }
    float v = acc / (1.f + __expf(-acc));
    g_xc[dir][idx] = v;
    fsplit(v, &g_xc_hi[dir][idx], &g_xc_lo[dir][idx]);
}

// ---------------------------------------------------------------------------
// Selective scan + D-skip + silu(z) gating -> bf16 hi/lo y
// ---------------------------------------------------------------------------
#define SCAN_TD 128
#define TCH 64

__global__ __launch_bounds__(SCAN_TD)
void k_scan(const float* __restrict__ alF, const float* __restrict__ alB,
            const float* __restrict__ dpF, const float* __restrict__ dpB) {
    int dir = blockIdx.z;
    int b = blockIdx.y;
    int d = blockIdx.x * SCAN_TD + threadIdx.x;

    const float* Alog = (dir ? alB : alF) + (size_t)d * DS;
    float Arow[DS];
    bool fastA = true;
    #pragma unroll
    for (int n = 0; n < DS; n++) {
        Arow[n] = -__expf(Alog[n]);
        float tgt = -(float)(n+1);
        fastA = fastA && (fabsf(Arow[n] - tgt) <= 1e-4f * (float)(n+1));
    }
    float Dv = (dir ? dpB : dpF)[d];

    float h[DS];
    #pragma unroll
    for (int n = 0; n < DS; n++) h[n] = 0.f;

    __shared__ float sB[TCH][DS];
    __shared__ float sC[TCH][DS];

    const float* dbl  = g_dbl[dir];
    const float* delt = g_delta[dir];
    const float* xcb  = g_xc[dir];
    const float* xzb  = g_xz[dir];
    bf16* yh = g_y_hi[dir];
    bf16* yl = g_y_lo[dir];

    for (int t0 = 0; t0 < LSEQ; t0 += TCH) {
        for (int i = threadIdx.x; i < TCH*DS; i += SCAN_TD) {
            int tt = i / DS, n = i % DS;
            size_t r = (size_t)(b*LSEQ + t0 + tt);
            sB[tt][n] = dbl[r*DBLW + DTR + n];
            sC[tt][n] = dbl[r*DBLW + DTR + DS + n];
        }
        __syncthreads();
        if (fastA) {
            for (int tt = 0; tt < TCH; tt++) {
                size_t r = (size_t)(b*LSEQ + t0 + tt);
                float dv = delt[r*DI + d];
                float xv = xcb[r*DI + d];
                float du = dv * xv;
                float e1 = __expf(-dv);
                float p = e1;
                float y = 0.f;
                #pragma unroll
                for (int n = 0; n < DS; n++) {
                    h[n] = h[n]*p + du*sB[tt][n];
                    y += h[n]*sC[tt][n];
                    p *= e1;
                }
                float zv = xzb[r*2*DI + DI + d];
                float yv = (y + xv*Dv) * (zv / (1.f + __expf(-zv)));
                fsplit(yv, yh + r*DI + d, yl + r*DI + d);
            }
        } else {
            for (int tt = 0; tt < TCH; tt++) {
                size_t r = (size_t)(b*LSEQ + t0 + tt);
                float dv = delt[r*DI + d];
                float xv = xcb[r*DI + d];
                float du = dv * xv;
                float y = 0.f;
                #pragma unroll
                for (int n = 0; n < DS; n++) {
                    float e = __expf(dv * Arow[n]);
                    h[n] = h[n]*e + du*sB[tt][n];
                    y += h[n]*sC[tt][n];
                }
                float zv = xzb[r*2*DI + DI + d];
                float yv = (y + xv*Dv) * (zv / (1.f + __expf(-zv)));
                fsplit(yv, yh + r*DI + d, yl + r*DI + d);
            }
        }
        __syncthreads();
    }
}

// ---------------------------------------------------------------------------
// Host launcher
// ---------------------------------------------------------------------------
extern "C" void kernel_launch(void* const* d_in, const int* in_sizes, int n_in,
                              void* d_out, int out_size) {
    (void)in_sizes; (void)n_in; (void)out_size;
    const int* ids = (const int*)d_in[0];
    const float* F[11]; const float* Bw[11];
    for (int i = 0; i < 11; i++) {
        F[i]  = (const float*)d_in[1 + i];
        Bw[i] = (const float*)d_in[12 + i];
    }
    float* out = (float*)d_out;

    static int smem_set = 0;
    if (!smem_set) {
        cudaFuncSetAttribute(k_gemm, cudaFuncAttributeMaxDynamicSharedMemorySize, GEMM_SMEM);
        smem_set = 1;
    }

    // ---- weight split (all layers, both dirs) ----
    bf16 *wip_hi[2], *wip_lo[2], *wxp_hi[2], *wxp_lo[2];
    bf16 *wdt_hi[2], *wdt_lo[2], *wop_hi[2], *wop_lo[2];
    {
        void* p;
        cudaGetSymbolAddress(&p, g_wip_hi); wip_hi[0]=(bf16*)p; wip_hi[1]=(bf16*)p + (size_t)NL*2*DI*DM;
        cudaGetSymbolAddress(&p, g_wip_lo); wip_lo[0]=(bf16*)p; wip_lo[1]=(bf16*)p + (size_t)NL*2*DI*DM;
        cudaGetSymbolAddress(&p, g_wxp_hi); wxp_hi[0]=(bf16*)p; wxp_hi[1]=(bf16*)p + (size_t)NL*DBLW*DI;
        cudaGetSymbolAddress(&p, g_wxp_lo); wxp_lo[0]=(bf16*)p; wxp_lo[1]=(bf16*)p + (size_t)NL*DBLW*DI;
        cudaGetSymbolAddress(&p, g_wdt_hi); wdt_hi[0]=(bf16*)p; wdt_hi[1]=(bf16*)p + (size_t)NL*DI*DTR;
        cudaGetSymbolAddress(&p, g_wdt_lo); wdt_lo[0]=(bf16*)p; wdt_lo[1]=(bf16*)p + (size_t)NL*DI*DTR;
        cudaGetSymbolAddress(&p, g_wop_hi); wop_hi[0]=(bf16*)p; wop_hi[1]=(bf16*)p + (size_t)NL*DM*DI;
        cudaGetSymbolAddress(&p, g_wop_lo); wop_lo[0]=(bf16*)p; wop_lo[1]=(bf16*)p + (size_t)NL*DM*DI;
    }
    for (int dir = 0; dir < 2; dir++) {
        const float* W2 = dir ? Bw[2] : F[2];
        const float* W5 = dir ? Bw[5] : F[5];
        const float* W6 = dir ? Bw[6] : F[6];
        const float* W10 = dir ? Bw[10] : F[10];
        int n;
        n = NL*2*DI*DM/4;
        k_wsplit<<<(n+255)/256, 256>>>((const float4*)W2, (bf162*)wip_hi[dir], (bf162*)wip_lo[dir], n);
        n = NL*DBLW*DI/4;
        k_wsplit<<<(n+255)/256, 256>>>((const float4*)W5, (bf162*)wxp_hi[dir], (bf162*)wxp_lo[dir], n);
        n = NL*DI*DTR/4;
        k_wsplit<<<(n+255)/256, 256>>>((const float4*)W6, (bf162*)wdt_hi[dir], (bf162*)wdt_lo[dir], n);
        n = NL*DM*DI/4;
        k_wsplit<<<(n+255)/256, 256>>>((const float4*)W10, (bf162*)wop_hi[dir], (bf162*)wop_lo[dir], n);
    }

    k_embed<<<dim3(RWS, 2), 192>>>(ids, F[0], Bw[0]);

    for (int layer = 0; layer < NL; layer++) {
        const float* nwF = F[1]  + (size_t)layer*DM;
        const float* nwB = Bw[1] + (size_t)layer*DM;
        const float* cwF = F[3]  + (size_t)layer*DI*DC;
        const float* cwB = Bw[3] + (size_t)layer*DI*DC;
        const float* cbF = F[4]  + (size_t)layer*DI;
        const float* cbB = Bw[4] + (size_t)layer*DI;
        const float* dbF = F[7]  + (size_t)layer*DI;
        const float* dbB = Bw[7] + (size_t)layer*DI;
        const float* alF = F[8]  + (size_t)layer*DI*DS;
        const float* alB = Bw[8] + (size_t)layer*DI*DS;
        const float* dpF = F[9]  + (size_t)layer*DI;
        const float* dpB = Bw[9] + (size_t)layer*DI;

        size_t oip = (size_t)layer*2*DI*DM;
        size_t oxp = (size_t)layer*DBLW*DI;
        size_t odt = (size_t)layer*DI*DTR;
        size_t oop = (size_t)layer*DM*DI;

        k_rmsnorm<<<dim3(RWS, 2), 256>>>(nwF, nwB);

        // in_proj: A=g_h, C=g_xz
        k_gemm<<<dim3(2*DI/128, RWS/128, 2), 256, GEMM_SMEM>>>(
            0, DM, wip_hi[0]+oip, wip_lo[0]+oip, wip_hi[1]+oip, wip_lo[1]+oip,
            1, 0, nullptr, RWS, 2*DI, DM, nullptr, nullptr, 0);

        k_conv<<<dim3(RWS*DI/256, 2), 256>>>(cwF, cwB, cbF, cbB);

        // x_proj: A=g_xc, C=g_dbl (f32 + bf16)
        k_gemm<<<dim3(1, RWS/128, 2), 256, GEMM_SMEM>>>(
            1, DI, wxp_hi[0]+oxp, wxp_lo[0]+oxp, wxp_hi[1]+oxp, wxp_lo[1]+oxp,
            3, 1, nullptr, RWS, DBLW, DI, nullptr, nullptr, 0);

        // delta: A=g_dbl (first 48 cols), C=g_delta, softplus epi
        k_gemm<<<dim3(DI/128, RWS/128, 2), 256, GEMM_SMEM>>>(
            2, DBLW, wdt_hi[0]+odt, wdt_lo[0]+odt, wdt_hi[1]+odt, wdt_lo[1]+odt,
            4, 0, nullptr, RWS, DI, DTR, dbF, dbB, 1);

        k_scan<<<dim3(DI/SCAN_TD, BSZ, 2), SCAN_TD>>>(alF, alB, dpF, dpB);

        // out_proj: A=g_y, C=g_x + d_out slice
        k_gemm<<<dim3(DM/128, RWS/128, 2), 256, GEMM_SMEM>>>(
            3, DI, wop_hi[0]+oop, wop_lo[0]+oop, wop_hi[1]+oop, wop_lo[1]+oop,
            6, 0, out + (size_t)layer*RWS*2*DM, RWS, DM, DI, nullptr, nullptr, 0);
    }
}

// round 6
// speedup vs baseline: 1.7106x; 1.0336x over previous
#include <cuda_runtime.h>
#include <cuda_bf16.h>
#include <cstdint>

#define BSZ 2
#define LSEQ 1024
#define DM 768
#define DI 1536
#define DS 16
#define DC 4
#define DTR 48
#define NL 24
#define RWS (BSZ*LSEQ)
#define DBLW (DTR + 2*DS)       /* 80 */
#define EPSF 1e-5f
#define XP_SLICES 8
#define XP_KLEN (DI/XP_SLICES)  /* 192 */

typedef __nv_bfloat16 bf16;
typedef __nv_bfloat162 bf162;

// ---------------------------------------------------------------------------
// Scratch
// ---------------------------------------------------------------------------
__device__ float g_x[2][RWS*DM];
__device__ float g_xz[2][RWS*2*DI];
__device__ float g_xc[2][RWS*DI];
__device__ float g_dbl[2][RWS*DBLW];
__device__ float g_delta[2][RWS*DI];
__device__ float g_xp_part[2][XP_SLICES][RWS*128];   // split-K partials

__device__ bf16 g_h_hi[2][RWS*DM],   g_h_lo[2][RWS*DM];
__device__ bf16 g_xc_hi[2][RWS*DI],  g_xc_lo[2][RWS*DI];
__device__ bf16 g_dbl_hi[2][RWS*DBLW], g_dbl_lo[2][RWS*DBLW];
__device__ bf16 g_y_hi[2][RWS*DI],   g_y_lo[2][RWS*DI];

__device__ bf16 g_wip_hi[2][NL*2*DI*DM], g_wip_lo[2][NL*2*DI*DM];
__device__ bf16 g_wxp_hi[2][NL*DBLW*DI], g_wxp_lo[2][NL*DBLW*DI];
__device__ bf16 g_wdt_hi[2][NL*DI*DTR],  g_wdt_lo[2][NL*DI*DTR];
__device__ bf16 g_wop_hi[2][NL*DM*DI],   g_wop_lo[2][NL*DM*DI];

__device__ __forceinline__ float* getCf(int w, int dir) {
    switch (w) {
        case 1: return g_xz[dir];
        case 4: return g_delta[dir];
        default: return g_x[dir];
    }
}

__device__ __forceinline__ uint32_t smem_u32(const void* p) {
    uint32_t a;
    asm("{ .reg .u64 t; cvta.to.shared.u64 t, %1; cvt.u32.u64 %0, t; }" : "=r"(a) : "l"(p));
    return a;
}

__device__ __forceinline__ void fsplit(float v, bf16* hp, bf16* lp) {
    bf16 h = __float2bfloat16_rn(v);
    *hp = h;
    *lp = __float2bfloat16_rn(v - __bfloat162float(h));
}

#define CP16(dst, src, sz) \
    asm volatile("cp.async.cg.shared.global [%0], [%1], 16, %2;" \
        :: "r"(dst), "l"(src), "r"(sz) : "memory")
#define CP_COMMIT() asm volatile("cp.async.commit_group;" ::: "memory")
#define CP_WAIT1()  asm volatile("cp.async.wait_group 1;" ::: "memory")
#define CP_WAIT0()  asm volatile("cp.async.wait_group 0;" ::: "memory")

#define LDSM4(r, addr) \
    asm volatile("ldmatrix.sync.aligned.m8n8.x4.shared.b16 {%0,%1,%2,%3}, [%4];" \
        : "=r"((r)[0]), "=r"((r)[1]), "=r"((r)[2]), "=r"((r)[3]) : "r"(addr))

#define MMA16816(c, a, b0v, b1v) \
    asm volatile("mma.sync.aligned.m16n8k16.row.col.f32.bf16.bf16.f32 " \
        "{%0,%1,%2,%3}, {%4,%5,%6,%7}, {%8,%9}, {%0,%1,%2,%3};" \
        : "+f"((c)[0]), "+f"((c)[1]), "+f"((c)[2]), "+f"((c)[3]) \
        : "r"((a)[0]), "r"((a)[1]), "r"((a)[2]), "r"((a)[3]), "r"(b0v), "r"(b1v))

// ---------------------------------------------------------------------------
// Weight split kernels
// ---------------------------------------------------------------------------
__global__ void k_wsplit(const float4* __restrict__ sF, const float4* __restrict__ sB,
                         bf162* __restrict__ hF, bf162* __restrict__ lF,
                         bf162* __restrict__ hB, bf162* __restrict__ lB, int n4) {
    int i = blockIdx.x * blockDim.x + threadIdx.x;
    if (i >= n4) return;
    const float4* src = blockIdx.y ? sB : sF;
    bf162* hi = blockIdx.y ? hB : hF;
    bf162* lo = blockIdx.y ? lB : lF;
    float4 v = src[i];
    bf162 h01 = __floats2bfloat162_rn(v.x, v.y);
    bf162 h23 = __floats2bfloat162_rn(v.z, v.w);
    bf162 l01 = __floats2bfloat162_rn(v.x - __bfloat162float(h01.x),
                                      v.y - __bfloat162float(h01.y));
    bf162 l23 = __floats2bfloat162_rn(v.z - __bfloat162float(h23.x),
                                      v.w - __bfloat162float(h23.y));
    hi[i*2] = h01; hi[i*2+1] = h23;
    lo[i*2] = l01; lo[i*2+1] = l23;
}

__global__ void k_wsplit2(const float4* __restrict__ s0F, const float4* __restrict__ s0B,
                          bf162* __restrict__ h0F, bf162* __restrict__ l0F,
                          bf162* __restrict__ h0B, bf162* __restrict__ l0B, int n40,
                          const float4* __restrict__ s1F, const float4* __restrict__ s1B,
                          bf162* __restrict__ h1F, bf162* __restrict__ l1F,
                          bf162* __restrict__ h1B, bf162* __restrict__ l1B, int n41) {
    int i = blockIdx.x * blockDim.x + threadIdx.x;
    int set = blockIdx.y >> 1, dir = blockIdx.y & 1;
    const float4* src; bf162 *hi, *lo; int n4;
    if (set == 0) { src = dir ? s0B : s0F; hi = dir ? h0B : h0F; lo = dir ? l0B : l0F; n4 = n40; }
    else          { src = dir ? s1B : s1F; hi = dir ? h1B : h1F; lo = dir ? l1B : l1F; n4 = n41; }
    if (i >= n4) return;
    float4 v = src[i];
    bf162 h01 = __floats2bfloat162_rn(v.x, v.y);
    bf162 h23 = __floats2bfloat162_rn(v.z, v.w);
    bf162 l01 = __floats2bfloat162_rn(v.x - __bfloat162float(h01.x),
                                      v.y - __bfloat162float(h01.y));
    bf162 l23 = __floats2bfloat162_rn(v.z - __bfloat162float(h23.x),
                                      v.w - __bfloat162float(h23.y));
    hi[i*2] = h01; hi[i*2+1] = h23;
    lo[i*2] = l01; lo[i*2+1] = l23;
}

// ---------------------------------------------------------------------------
// Embedding
// ---------------------------------------------------------------------------
__global__ void k_embed(const int* __restrict__ ids,
                        const float* __restrict__ embF,
                        const float* __restrict__ embB) {
    int row = blockIdx.x, dir = blockIdx.y;
    int b = row / LSEQ, l = row % LSEQ;
    int tok = (dir == 0) ? ids[b*LSEQ + l] : ids[b*LSEQ + (LSEQ-1-l)];
    const float* emb = (dir == 0) ? embF : embB;
    const float4* src = (const float4*)(emb + (size_t)tok * DM);
    float4* dst = (float4*)(g_x[dir] + (size_t)row * DM);
    for (int i = threadIdx.x; i < DM/4; i += blockDim.x) dst[i] = src[i];
}

// ---------------------------------------------------------------------------
// RMSNorm -> bf16 hi/lo
// ---------------------------------------------------------------------------
__global__ void k_rmsnorm(const float* __restrict__ wF, const float* __restrict__ wB) {
    int row = blockIdx.x, dir = blockIdx.y;
    const float* x = g_x[dir] + (size_t)row * DM;
    bf16* hh = g_h_hi[dir] + (size_t)row * DM;
    bf16* hl = g_h_lo[dir] + (size_t)row * DM;
    const float* w = dir ? wB : wF;
    float s = 0.f;
    for (int i = threadIdx.x; i < DM; i += 256) { float v = x[i]; s += v*v; }
    #pragma unroll
    for (int o = 16; o; o >>= 1) s += __shfl_down_sync(0xffffffffu, s, o);
    __shared__ float red[8];
    if ((threadIdx.x & 31) == 0) red[threadIdx.x >> 5] = s;
    __syncthreads();
    if (threadIdx.x < 8) {
        float t = red[threadIdx.x];
        #pragma unroll
        for (int o = 4; o; o >>= 1) t += __shfl_down_sync(0xffu, t, o);
        if (threadIdx.x == 0) red[0] = t;
    }
    __syncthreads();
    float inv = rsqrtf(red[0] / (float)DM + EPSF);
    for (int i = threadIdx.x; i < DM; i += 256) {
        float v = x[i] * inv * w[i];
        fsplit(v, hh + i, hl + i);
    }
}

// ---------------------------------------------------------------------------
// Split-bf16 HMMA GEMM, 512 threads (16 warps, 4M x 4N), warp tile 32x32.
// cp.async double-buffered, K chunks of 64.  Optional split-K partial mode.
// ---------------------------------------------------------------------------
#define GTK 64
#define STAGE_B 65536
#define GEMM_SMEM (2*STAGE_B)

__device__ __forceinline__ void stage_tiles(
    uint32_t stg,
    const bf16* __restrict__ Ahi, const bf16* __restrict__ Alo,
    const bf16* __restrict__ Whi, const bf16* __restrict__ Wlo,
    int m0, int n0, int k0, int lda, int ldw, int N, int K, int tid)
{
    #pragma unroll
    for (int t = 0; t < 2; t++) {
        int idx = tid + t*512;
        int row = idx >> 3, col = idx & 7;
        int kk = k0 + col*8;
        uint32_t soff = (uint32_t)(row*128 + ((col*16) ^ ((row & 7) << 4)));
        int asz = (kk < K) ? 16 : 0;
        size_t aoffm = (size_t)(m0+row)*lda + (asz ? kk : 0);
        CP16(stg + soff,          Ahi + aoffm, asz);
        CP16(stg + 16384 + soff,  Alo + aoffm, asz);
        int gn = n0 + row;
        int bsz = (gn < N && kk < K) ? 16 : 0;
        size_t boff = (size_t)(bsz ? gn : 0)*ldw + (bsz ? kk : 0);
        CP16(stg + 32768 + soff,  Whi + boff, bsz);
        CP16(stg + 49152 + soff,  Wlo + boff, bsz);
    }
}

__global__ __launch_bounds__(512, 1)
void k_gemm(int aId, int lda,
            const bf16* __restrict__ Whi0, const bf16* __restrict__ Wlo0,
            const bf16* __restrict__ Whi1, const bf16* __restrict__ Wlo1,
            int cfId, int cbfId, float* __restrict__ outp,
            int M, int N, int K,
            const float* __restrict__ b0, const float* __restrict__ b1,
            int epi, int splitK, float* __restrict__ partial) {
    extern __shared__ __align__(1024) char smem[];
    const int dir = blockIdx.z;
    const bf16 *Ahi, *Alo;
    switch (aId) {
        case 0: Ahi = g_h_hi[dir];   Alo = g_h_lo[dir];   break;
        case 1: Ahi = g_xc_hi[dir];  Alo = g_xc_lo[dir];  break;
        case 2: Ahi = g_dbl_hi[dir]; Alo = g_dbl_lo[dir]; break;
        default: Ahi = g_y_hi[dir];  Alo = g_y_lo[dir];   break;
    }
    const bf16* Whi = dir ? Whi1 : Whi0;
    const bf16* Wlo = dir ? Wlo1 : Wlo0;
    const float* bias = dir ? b1 : b0;

    const uint32_t tb = smem_u32(smem);
    const int tid = threadIdx.x;
    const int lane = tid & 31, wid = tid >> 5;
    const int wm = wid & 3, wn = wid >> 2;          // 4 x 4 warp grid
    const int m0 = blockIdx.y * 128;
    int n0, kbase, kLen, slice = 0;
    if (splitK) { slice = blockIdx.x; n0 = 0; kLen = XP_KLEN; kbase = slice * XP_KLEN; }
    else        { n0 = blockIdx.x * 128; kLen = K; kbase = 0; }

    const int l15 = lane & 15;
    const int a_kbx = (lane & 16) ? 16 : 0;
    const int b_nrow = (lane & 7) + ((lane & 16) ? 8 : 0);
    const int b_kbx = (lane & 8) ? 16 : 0;

    uint32_t aOff[2], aMsk[2];
    #pragma unroll
    for (int mt = 0; mt < 2; mt++) {
        int r = wm*32 + mt*16 + l15;
        aOff[mt] = r * 128;
        aMsk[mt] = (r & 7) << 4;
    }
    uint32_t bOff[2], bMsk[2];
    #pragma unroll
    for (int g = 0; g < 2; g++) {
        int r = wn*32 + g*16 + b_nrow;
        bOff[g] = r * 128;
        bMsk[g] = (r & 7) << 4;
    }

    float c[2][4][4];
    #pragma unroll
    for (int i = 0; i < 2; i++)
        #pragma unroll
        for (int j = 0; j < 4; j++)
            #pragma unroll
            for (int q = 0; q < 4; q++) c[i][j][q] = 0.f;

    const int nch = (kLen + GTK - 1) / GTK;
    stage_tiles(tb, Ahi, Alo, Whi, Wlo, m0, n0, kbase, lda, K, N, K, tid);
    CP_COMMIT();

    for (int ch = 0; ch < nch; ch++) {
        if (ch + 1 < nch) {
            stage_tiles(tb + ((ch+1)&1)*STAGE_B, Ahi, Alo, Whi, Wlo,
                        m0, n0, kbase + (ch+1)*GTK, lda, K, N, K, tid);
            CP_COMMIT();
            CP_WAIT1();
        } else {
            CP_WAIT0();
        }
        __syncthreads();

        const uint32_t AHI = tb + (ch&1)*STAGE_B;
        const uint32_t ALO = AHI + 16384, BHI = AHI + 32768, BLO = AHI + 49152;
        #pragma unroll
        for (int ks = 0; ks < 4; ks++) {
            const int kb = ks * 32;
            uint32_t ah[2][4], al[2][4], bh[2][4], bl[2][4];
            #pragma unroll
            for (int mt = 0; mt < 2; mt++) {
                uint32_t kx = (uint32_t)(kb + a_kbx) ^ aMsk[mt];
                LDSM4(ah[mt], AHI + aOff[mt] + kx);
                LDSM4(al[mt], ALO + aOff[mt] + kx);
            }
            #pragma unroll
            for (int g = 0; g < 2; g++) {
                uint32_t kx = (uint32_t)(kb + b_kbx) ^ bMsk[g];
                LDSM4(bh[g], BHI + bOff[g] + kx);
                LDSM4(bl[g], BLO + bOff[g] + kx);
            }
            #pragma unroll
            for (int mt = 0; mt < 2; mt++)
                #pragma unroll
                for (int nt = 0; nt < 4; nt++) {
                    int g = nt >> 1, o = (nt & 1) * 2;
                    float* cc = c[mt][nt];
                    MMA16816(cc, ah[mt], bh[g][o], bh[g][o+1]);
                    MMA16816(cc, ah[mt], bl[g][o], bl[g][o+1]);
                    MMA16816(cc, al[mt], bh[g][o], bh[g][o+1]);
                }
        }
        __syncthreads();
    }

    // ---- epilogue ----
    const int mrow = m0 + wm*32 + (lane >> 2);
    const int ncol0 = n0 + wn*32 + (lane & 3)*2;
    if (splitK) {
        float* pbase = partial + ((size_t)(dir*XP_SLICES + slice))*RWS*128;
        #pragma unroll
        for (int mt = 0; mt < 2; mt++)
            #pragma unroll
            for (int nt = 0; nt < 4; nt++) {
                int n = ncol0 + nt*8;
                #pragma unroll
                for (int half = 0; half < 2; half++) {
                    int m = mrow + mt*16 + half*8;
                    *(float2*)(pbase + (size_t)m*128 + n) =
                        make_float2(c[mt][nt][half*2], c[mt][nt][half*2+1]);
                }
            }
        return;
    }
    float* Cf = getCf(cfId, dir);
    #pragma unroll
    for (int mt = 0; mt < 2; mt++) {
        #pragma unroll
        for (int nt = 0; nt < 4; nt++) {
            int n = ncol0 + nt*8;
            if (n >= N) continue;
            #pragma unroll
            for (int half = 0; half < 2; half++) {
                int m = mrow + mt*16 + half*8;
                float v0 = c[mt][nt][half*2+0];
                float v1 = c[mt][nt][half*2+1];
                if (epi == 1) {
                    v0 += bias[n];   v1 += bias[n+1];
                    v0 = (v0 > 20.f) ? v0 : log1pf(__expf(v0));
                    v1 = (v1 > 20.f) ? v1 : log1pf(__expf(v1));
                }
                *(float2*)(Cf + (size_t)m*N + n) = make_float2(v0, v1);
                if (outp)
                    *(float2*)(outp + (size_t)m*(2*DM) + dir*DM + n) = make_float2(v0, v1);
            }
        }
    }
}

// ---------------------------------------------------------------------------
// Split-K reduce for x_proj: sum 8 partials -> g_dbl f32 + bf16 hi/lo
// ---------------------------------------------------------------------------
__global__ void k_xp_reduce() {
    int idx = blockIdx.x * blockDim.x + threadIdx.x;   // over RWS*DBLW
    int dir = blockIdx.y;
    if (idx >= RWS*DBLW) return;
    int m = idx / DBLW, n = idx % DBLW;
    const float* p = g_xp_part[dir][0] + (size_t)m*128 + n;
    float s = 0.f;
    #pragma unroll
    for (int sl = 0; sl < XP_SLICES; sl++) s += p[(size_t)sl*RWS*128];
    g_dbl[dir][idx] = s;
    fsplit(s, &g_dbl_hi[dir][idx], &g_dbl_lo[dir][idx]);
}

// ---------------------------------------------------------------------------
// Causal depthwise conv1d (k=4) + bias + SiLU -> f32 + bf16 hi/lo
// ---------------------------------------------------------------------------
__global__ void k_conv(const float* __restrict__ cwF, const float* __restrict__ cwB,
                       const float* __restrict__ cbF, const float* __restrict__ cbB) {
    int idx = blockIdx.x * blockDim.x + threadIdx.x;
    int dir = blockIdx.y;
    if (idx >= RWS*DI) return;
    int row = idx / DI, c = idx % DI;
    int b = row / LSEQ, l = row % LSEQ;
    const float* cw = (dir ? cwB : cwF) + c*DC;
    float acc = (dir ? cbB : cbF)[c];
    const float* xz = g_xz[dir];
    #pragma unroll
    for (int k = 0; k < DC; k++) {
        int ls = l - (DC-1) + k;
        if (ls >= 0) acc += xz[((size_t)(b*LSEQ + ls))*2*DI + c] * cw[k];
    }
    float v = acc / (1.f + __expf(-acc));
    g_xc[dir][idx] = v;
    fsplit(v, &g_xc_hi[dir][idx], &g_xc_lo[dir][idx]);
}

// ---------------------------------------------------------------------------
// Selective scan + D-skip + silu(z) gating -> bf16 hi/lo y
// ---------------------------------------------------------------------------
#define SCAN_TD 128
#define TCH 64

__global__ __launch_bounds__(SCAN_TD)
void k_scan(const float* __restrict__ alF, const float* __restrict__ alB,
            const float* __restrict__ dpF, const float* __restrict__ dpB) {
    int dir = blockIdx.z;
    int b = blockIdx.y;
    int d = blockIdx.x * SCAN_TD + threadIdx.x;

    const float* Alog = (dir ? alB : alF) + (size_t)d * DS;
    float Arow[DS];
    bool fastA = true;
    #pragma unroll
    for (int n = 0; n < DS; n++) {
        Arow[n] = -__expf(Alog[n]);
        float tgt = -(float)(n+1);
        fastA = fastA && (fabsf(Arow[n] - tgt) <= 1e-4f * (float)(n+1));
    }
    float Dv = (dir ? dpB : dpF)[d];

    float h[DS];
    #pragma unroll
    for (int n = 0; n < DS; n++) h[n] = 0.f;

    __shared__ float sB[TCH][DS];
    __shared__ float sC[TCH][DS];

    const float* dbl  = g_dbl[dir];
    const float* delt = g_delta[dir];
    const float* xcb  = g_xc[dir];
    const float* xzb  = g_xz[dir];
    bf16* yh = g_y_hi[dir];
    bf16* yl = g_y_lo[dir];

    for (int t0 = 0; t0 < LSEQ; t0 += TCH) {
        for (int i = threadIdx.x; i < TCH*DS; i += SCAN_TD) {
            int tt = i / DS, n = i % DS;
            size_t r = (size_t)(b*LSEQ + t0 + tt);
            sB[tt][n] = dbl[r*DBLW + DTR + n];
            sC[tt][n] = dbl[r*DBLW + DTR + DS + n];
        }
        __syncthreads();
        if (fastA) {
            for (int tt = 0; tt < TCH; tt++) {
                size_t r = (size_t)(b*LSEQ + t0 + tt);
                float dv = delt[r*DI + d];
                float xv = xcb[r*DI + d];
                float du = dv * xv;
                float e1 = __expf(-dv);
                float p = e1;
                float y = 0.f;
                #pragma unroll
                for (int n = 0; n < DS; n++) {
                    h[n] = h[n]*p + du*sB[tt][n];
                    y += h[n]*sC[tt][n];
                    p *= e1;
                }
                float zv = xzb[r*2*DI + DI + d];
                float yv = (y + xv*Dv) * (zv / (1.f + __expf(-zv)));
                fsplit(yv, yh + r*DI + d, yl + r*DI + d);
            }
        } else {
            for (int tt = 0; tt < TCH; tt++) {
                size_t r = (size_t)(b*LSEQ + t0 + tt);
                float dv = delt[r*DI + d];
                float xv = xcb[r*DI + d];
                float du = dv * xv;
                float y = 0.f;
                #pragma unroll
                for (int n = 0; n < DS; n++) {
                    float e = __expf(dv * Arow[n]);
                    h[n] = h[n]*e + du*sB[tt][n];
                    y += h[n]*sC[tt][n];
                }
                float zv = xzb[r*2*DI + DI + d];
                float yv = (y + xv*Dv) * (zv / (1.f + __expf(-zv)));
                fsplit(yv, yh + r*DI + d, yl + r*DI + d);
            }
        }
        __syncthreads();
    }
}

// ---------------------------------------------------------------------------
// Host launcher
// ---------------------------------------------------------------------------
extern "C" void kernel_launch(void* const* d_in, const int* in_sizes, int n_in,
                              void* d_out, int out_size) {
    (void)in_sizes; (void)n_in; (void)out_size;
    const int* ids = (const int*)d_in[0];
    const float* F[11]; const float* Bw[11];
    for (int i = 0; i < 11; i++) {
        F[i]  = (const float*)d_in[1 + i];
        Bw[i] = (const float*)d_in[12 + i];
    }
    float* out = (float*)d_out;

    static int smem_set = 0;
    if (!smem_set) {
        cudaFuncSetAttribute(k_gemm, cudaFuncAttributeMaxDynamicSharedMemorySize, GEMM_SMEM);
        smem_set = 1;
    }

    bf16 *wip_hi[2], *wip_lo[2], *wxp_hi[2], *wxp_lo[2];
    bf16 *wdt_hi[2], *wdt_lo[2], *wop_hi[2], *wop_lo[2];
    float* xp_part;
    {
        void* p;
        cudaGetSymbolAddress(&p, g_wip_hi); wip_hi[0]=(bf16*)p; wip_hi[1]=(bf16*)p + (size_t)NL*2*DI*DM;
        cudaGetSymbolAddress(&p, g_wip_lo); wip_lo[0]=(bf16*)p; wip_lo[1]=(bf16*)p + (size_t)NL*2*DI*DM;
        cudaGetSymbolAddress(&p, g_wxp_hi); wxp_hi[0]=(bf16*)p; wxp_hi[1]=(bf16*)p + (size_t)NL*DBLW*DI;
        cudaGetSymbolAddress(&p, g_wxp_lo); wxp_lo[0]=(bf16*)p; wxp_lo[1]=(bf16*)p + (size_t)NL*DBLW*DI;
        cudaGetSymbolAddress(&p, g_wdt_hi); wdt_hi[0]=(bf16*)p; wdt_hi[1]=(bf16*)p + (size_t)NL*DI*DTR;
        cudaGetSymbolAddress(&p, g_wdt_lo); wdt_lo[0]=(bf16*)p; wdt_lo[1]=(bf16*)p + (size_t)NL*DI*DTR;
        cudaGetSymbolAddress(&p, g_wop_hi); wop_hi[0]=(bf16*)p; wop_hi[1]=(bf16*)p + (size_t)NL*DM*DI;
        cudaGetSymbolAddress(&p, g_wop_lo); wop_lo[0]=(bf16*)p; wop_lo[1]=(bf16*)p + (size_t)NL*DM*DI;
        cudaGetSymbolAddress(&p, g_xp_part); xp_part = (float*)p;
    }

    // Launch 1: in_proj weight split (both dirs)
    {
        int n4 = NL*2*DI*DM/4;
        k_wsplit<<<dim3((n4+255)/256, 2), 256>>>(
            (const float4*)F[2], (const float4*)Bw[2],
            (bf162*)wip_hi[0], (bf162*)wip_lo[0], (bf162*)wip_hi[1], (bf162*)wip_lo[1], n4);
    }
    // Launch 2: out_proj weight split
    {
        int n4 = NL*DM*DI/4;
        k_wsplit<<<dim3((n4+255)/256, 2), 256>>>(
            (const float4*)F[10], (const float4*)Bw[10],
            (bf162*)wop_hi[0], (bf162*)wop_lo[0], (bf162*)wop_hi[1], (bf162*)wop_lo[1], n4);
    }
    // Launch 3: x_proj + dt weight split
    {
        int n40 = NL*DBLW*DI/4, n41 = NL*DI*DTR/4;
        int gx = ((n40 > n41 ? n40 : n41) + 255)/256;
        k_wsplit2<<<dim3(gx, 4), 256>>>(
            (const float4*)F[5], (const float4*)Bw[5],
            (bf162*)wxp_hi[0], (bf162*)wxp_lo[0], (bf162*)wxp_hi[1], (bf162*)wxp_lo[1], n40,
            (const float4*)F[6], (const float4*)Bw[6],
            (bf162*)wdt_hi[0], (bf162*)wdt_lo[0], (bf162*)wdt_hi[1], (bf162*)wdt_lo[1], n41);
    }
    // Launch 4: embedding
    k_embed<<<dim3(RWS, 2), 192>>>(ids, F[0], Bw[0]);

    for (int layer = 0; layer < NL; layer++) {
        const float* nwF = F[1]  + (size_t)layer*DM;
        const float* nwB = Bw[1] + (size_t)layer*DM;
        const float* cwF = F[3]  + (size_t)layer*DI*DC;
        const float* cwB = Bw[3] + (size_t)layer*DI*DC;
        const float* cbF = F[4]  + (size_t)layer*DI;
        const float* cbB = Bw[4] + (size_t)layer*DI;
        const float* dbF = F[7]  + (size_t)layer*DI;
        const float* dbB = Bw[7] + (size_t)layer*DI;
        const float* alF = F[8]  + (size_t)layer*DI*DS;
        const float* alB = Bw[8] + (size_t)layer*DI*DS;
        const float* dpF = F[9]  + (size_t)layer*DI;
        const float* dpB = Bw[9] + (size_t)layer*DI;

        size_t oip = (size_t)layer*2*DI*DM;
        size_t oxp = (size_t)layer*DBLW*DI;
        size_t odt = (size_t)layer*DI*DTR;
        size_t oop = (size_t)layer*DM*DI;

        // Launch 5 (layer 0): rmsnorm
        k_rmsnorm<<<dim3(RWS, 2), 256>>>(nwF, nwB);

        // Launch 6 (layer 0): in_proj  <-- ncu -s 5 -c 1 captures this
        k_gemm<<<dim3(2*DI/128, RWS/128, 2), 512, GEMM_SMEM>>>(
            0, DM, wip_hi[0]+oip, wip_lo[0]+oip, wip_hi[1]+oip, wip_lo[1]+oip,
            1, 0, nullptr, RWS, 2*DI, DM, nullptr, nullptr, 0, 0, nullptr);

        k_conv<<<dim3(RWS*DI/256, 2), 256>>>(cwF, cwB, cbF, cbB);

        // x_proj split-K: 8 slices -> partials
        k_gemm<<<dim3(XP_SLICES, RWS/128, 2), 512, GEMM_SMEM>>>(
            1, DI, wxp_hi[0]+oxp, wxp_lo[0]+oxp, wxp_hi[1]+oxp, wxp_lo[1]+oxp,
            0, 0, nullptr, RWS, DBLW, DI, nullptr, nullptr, 0, 1, xp_part);
        k_xp_reduce<<<dim3((RWS*DBLW+255)/256, 2), 256>>>();

        // delta: softplus epi
        k_gemm<<<dim3(DI/128, RWS/128, 2), 512, GEMM_SMEM>>>(
            2, DBLW, wdt_hi[0]+odt, wdt_lo[0]+odt, wdt_hi[1]+odt, wdt_lo[1]+odt,
            4, 0, nullptr, RWS, DI, DTR, dbF, dbB, 1, 0, nullptr);

        k_scan<<<dim3(DI/SCAN_TD, BSZ, 2), SCAN_TD>>>(alF, alB, dpF, dpB);

        // out_proj + fused d_out write
        k_gemm<<<dim3(DM/128, RWS/128, 2), 512, GEMM_SMEM>>>(
            3, DI, wop_hi[0]+oop, wop_lo[0]+oop, wop_hi[1]+oop, wop_lo[1]+oop,
            6, 0, out + (size_t)layer*RWS*2*DM, RWS, DM, DI, nullptr, nullptr, 0, 0, nullptr);
    }
}